// round 1
// baseline (speedup 1.0000x reference)
#include <cuda_runtime.h>

#define D       128
#define N_SRC   40000
#define N_TGT   40000
#define N_EDGE  640000
#define TILE_M  128
#define KC      32
#define SST     132   // padded smem stride (floats)

// Scratch for scatter-mean (static __device__ allocation is allowed)
__device__ float g_sums[(long)N_TGT * D];
__device__ float g_counts[N_TGT];

__global__ void zero_scratch_kernel() {
    const int n = N_TGT * D;
    const int total = n + N_TGT;
    for (int i = blockIdx.x * blockDim.x + threadIdx.x; i < total;
         i += gridDim.x * blockDim.x) {
        if (i < n) g_sums[i] = 0.f;
        else       g_counts[i - n] = 0.f;
    }
}

// Fused: Y = silu(X0 @ W1^T + X1 @ W2^T); A = LN(Y)*gamma+beta;
// out = residual + A; EDGE additionally scatter-adds A into g_sums / g_counts.
//
// EDGE:  X0[m] = src_feat[src_idx[m]] + tgt_feat[tgt_idx[m]], X1 = residual = edge_feat
// NODE:  X0[m] = g_sums[m] / max(count,1),                    X1 = residual = tgt_feat
template <bool EDGE>
__global__ __launch_bounds__(256)
void fused_gemm_ln_kernel(const float* __restrict__ featA,   // EDGE: src_feat, NODE: unused
                          const float* __restrict__ featB,   // EDGE: tgt_feat, NODE: unused
                          const float* __restrict__ featX,   // EDGE: edge_feat, NODE: tgt_feat
                          const float* __restrict__ W1,
                          const float* __restrict__ W2,
                          const float* __restrict__ gamma,
                          const float* __restrict__ beta,
                          const int*   __restrict__ src_idx,
                          const int*   __restrict__ tgt_idx,
                          float*       __restrict__ out,
                          int M) {
    __shared__ float xs[KC][SST];
    __shared__ float ws[KC][SST];
    __shared__ int   s_si[TILE_M];
    __shared__ int   s_ti[TILE_M];
    __shared__ float s_inv[TILE_M];

    const int tid = threadIdx.x;
    const int tx  = tid & 15;   // output-col group
    const int ty  = tid >> 4;   // row group
    const int m0  = blockIdx.x * TILE_M;

    if (EDGE) {
        for (int i = tid; i < TILE_M; i += 256) {
            int e = m0 + i;
            s_si[i] = src_idx[e];
            s_ti[i] = tgt_idx[e];
        }
    } else {
        for (int i = tid; i < TILE_M; i += 256) {
            int r = m0 + i;
            s_inv[i] = (r < M) ? 1.f / fmaxf(g_counts[r], 1.f) : 0.f;
        }
    }
    __syncthreads();

    float acc[8][8];
#pragma unroll
    for (int r = 0; r < 8; r++)
#pragma unroll
        for (int c = 0; c < 8; c++) acc[r][c] = 0.f;

#pragma unroll 1
    for (int pass = 0; pass < 2; pass++) {
        const float* __restrict__ W = pass ? W2 : W1;
#pragma unroll 1
        for (int kc = 0; kc < D / KC; kc++) {
            const int k0 = kc * KC;
            // stage weights transposed: ws[k][n] = W[n][k0+k]
            for (int i = tid; i < D * KC; i += 256) {
                int n  = i >> 5;
                int kl = i & 31;
                ws[kl][n] = W[n * D + k0 + kl];
            }
            // stage inputs transposed: xs[k][m]
            for (int i = tid; i < TILE_M * KC; i += 256) {
                int m  = i >> 5;
                int kl = i & 31;
                float v;
                long  gm = (long)(m0 + m);
                if (EDGE) {
                    if (pass == 0)
                        v = featA[(long)s_si[m] * D + k0 + kl] +
                            featB[(long)s_ti[m] * D + k0 + kl];
                    else
                        v = featX[gm * D + k0 + kl];
                } else {
                    if (gm < M) {
                        if (pass == 0)
                            v = g_sums[gm * D + k0 + kl] * s_inv[m];
                        else
                            v = featX[gm * D + k0 + kl];
                    } else {
                        v = 0.f;
                    }
                }
                xs[kl][m] = v;
            }
            __syncthreads();
#pragma unroll
            for (int k = 0; k < KC; k++) {
                float4 xa = *(const float4*)&xs[k][ty * 4];
                float4 xb = *(const float4*)&xs[k][64 + ty * 4];
                float4 wa = *(const float4*)&ws[k][tx * 4];
                float4 wb = *(const float4*)&ws[k][64 + tx * 4];
                float xv[8] = {xa.x, xa.y, xa.z, xa.w, xb.x, xb.y, xb.z, xb.w};
                float wv[8] = {wa.x, wa.y, wa.z, wa.w, wb.x, wb.y, wb.z, wb.w};
#pragma unroll
                for (int r = 0; r < 8; r++)
#pragma unroll
                    for (int c = 0; c < 8; c++) acc[r][c] += xv[r] * wv[c];
            }
            __syncthreads();
        }
    }

    // ---------------- epilogue: silu + layernorm + residual (+ scatter) -----
    float g[8], b[8];
#pragma unroll
    for (int c = 0; c < 8; c++) {
        int n = (c < 4) ? (tx * 4 + c) : (64 + tx * 4 + (c - 4));
        g[c] = gamma[n];
        b[c] = beta[n];
    }

#pragma unroll
    for (int r = 0; r < 8; r++) {
        const int mrow = (r < 4) ? (ty * 4 + r) : (64 + ty * 4 + (r - 4));
        const long gm  = (long)(m0 + mrow);

        float sum = 0.f, sq = 0.f;
#pragma unroll
        for (int c = 0; c < 8; c++) {
            float v  = acc[r][c];
            float sv = v / (1.f + __expf(-v));   // silu
            acc[r][c] = sv;
            sum += sv;
            sq  += sv * sv;
        }
        // reduce across the 16 lanes sharing this row (same ty group)
#pragma unroll
        for (int o = 8; o >= 1; o >>= 1) {
            sum += __shfl_xor_sync(0xffffffffu, sum, o);
            sq  += __shfl_xor_sync(0xffffffffu, sq,  o);
        }
        const float mean = sum * (1.f / 128.f);
        const float var  = sq * (1.f / 128.f) - mean * mean;
        const float inv  = rsqrtf(var + 1e-5f);

        float add[8];
#pragma unroll
        for (int c = 0; c < 8; c++) add[c] = (acc[r][c] - mean) * inv * g[c] + b[c];

        if (!EDGE && gm >= M) continue;

        const float* __restrict__ resrow = featX + gm * D;
        float4 r0 = *(const float4*)&resrow[tx * 4];
        float4 r1 = *(const float4*)&resrow[64 + tx * 4];
        float4 o0 = make_float4(r0.x + add[0], r0.y + add[1], r0.z + add[2], r0.w + add[3]);
        float4 o1 = make_float4(r1.x + add[4], r1.y + add[5], r1.z + add[6], r1.w + add[7]);
        *(float4*)&out[gm * D + tx * 4]      = o0;
        *(float4*)&out[gm * D + 64 + tx * 4] = o1;

        if (EDGE) {
            const int t = s_ti[mrow];
            float* __restrict__ srow = g_sums + (long)t * D;
#pragma unroll
            for (int c = 0; c < 4; c++) atomicAdd(&srow[tx * 4 + c],      add[c]);
#pragma unroll
            for (int c = 0; c < 4; c++) atomicAdd(&srow[64 + tx * 4 + c], add[4 + c]);
            if (tx == 0) atomicAdd(&g_counts[t], 1.f);
        }
    }
}

extern "C" void kernel_launch(void* const* d_in, const int* in_sizes, int n_in,
                              void* d_out, int out_size) {
    const float* src_feat  = (const float*)d_in[0];
    const float* tgt_feat  = (const float*)d_in[1];
    const float* edge_feat = (const float*)d_in[2];
    const float* Ws2e      = (const float*)d_in[3];
    const float* We2e      = (const float*)d_in[4];
    const float* We2t      = (const float*)d_in[5];
    const float* Wt2t      = (const float*)d_in[6];
    const float* gamma1    = (const float*)d_in[7];
    const float* beta1     = (const float*)d_in[8];
    const float* gamma2    = (const float*)d_in[9];
    const float* beta2     = (const float*)d_in[10];
    const int*   src_idx   = (const int*)d_in[11];
    const int*   tgt_idx   = (const int*)d_in[12];
    float*       out       = (float*)d_out;

    zero_scratch_kernel<<<2048, 256>>>();

    fused_gemm_ln_kernel<true><<<N_EDGE / TILE_M, 256>>>(
        src_feat, tgt_feat, edge_feat, Ws2e, We2e, gamma1, beta1,
        src_idx, tgt_idx, out, N_EDGE);

    fused_gemm_ln_kernel<false><<<(N_TGT + TILE_M - 1) / TILE_M, 256>>>(
        nullptr, nullptr, tgt_feat, We2t, Wt2t,
        gamma2, beta2, nullptr, nullptr, out + (long)N_EDGE * D, N_TGT);
}

// round 4
// speedup vs baseline: 1.9615x; 1.9615x over previous
#include <cuda_runtime.h>
#include <cstdint>

#define D 128
#define N_TGT 40000
#define N_EDGE 640000
#define NTILES (N_EDGE / 128)
#define PAD 132   // fp32 smem row stride

// ---------------- scratch ----------------
__device__ float g_sums[(size_t)N_TGT * D];
__device__ float g_counts[N_TGT];

__global__ void zero_scratch_kernel() {
    const int n = N_TGT * D;
    const int total = n + N_TGT;
    for (int i = blockIdx.x * blockDim.x + threadIdx.x; i < total;
         i += gridDim.x * blockDim.x) {
        if (i < n) g_sums[i] = 0.f;
        else       g_counts[i - n] = 0.f;
    }
}

// ---------------- helpers ----------------
__device__ __forceinline__ float to_tf32(float x) {
    float r;
    asm("cvt.rna.tf32.f32 %0, %1;" : "=f"(r) : "f"(x));
    return r;
}
__device__ __forceinline__ uint32_t f2u(float x) { return __float_as_uint(x); }

// D += A(m16k8) * B(k8n8), tf32
__device__ __forceinline__ void mma8(float* d, const uint32_t* a,
                                     uint32_t b0, uint32_t b1) {
    asm volatile(
        "mma.sync.aligned.m16n8k8.row.col.f32.tf32.tf32.f32 "
        "{%0,%1,%2,%3}, {%4,%5,%6,%7}, {%8,%9}, {%0,%1,%2,%3};"
        : "+f"(d[0]), "+f"(d[1]), "+f"(d[2]), "+f"(d[3])
        : "r"(a[0]), "r"(a[1]), "r"(a[2]), "r"(a[3]), "r"(b0), "r"(b1));
}

// ---------------- smem layout (float offsets) ----------------
#define SOFF_W1   0
#define SOFF_W2   (128 * PAD)            // 16896
#define SOFF_X    (2 * 128 * PAD)        // 33792
#define SOFF_SUM  (3 * 128 * PAD)        // 50688: sum[2][128]
#define SOFF_SQ   (SOFF_SUM + 256)       // sq[2][128]
#define SOFF_SI   (SOFF_SQ + 256)        // 128 ints
#define SOFF_TI   (SOFF_SI + 128)
#define SOFF_G    (SOFF_TI + 128)
#define SOFF_B    (SOFF_G + 128)
#define SMEM_FLOATS (SOFF_B + 128)
#define SMEM_BYTES  (SMEM_FLOATS * 4)    // 206848

// ======================= EDGE kernel (mma.sync tf32) =======================
__global__ void __launch_bounds__(256, 1)
edge_kernel(const float* __restrict__ src_feat,
            const float* __restrict__ tgt_feat,
            const float* __restrict__ edge_feat,
            const float* __restrict__ W1,
            const float* __restrict__ W2,
            const float* __restrict__ gamma,
            const float* __restrict__ beta,
            const int*   __restrict__ src_idx,
            const int*   __restrict__ tgt_idx,
            float*       __restrict__ out)
{
    extern __shared__ float sm[];
    float* W1s   = sm + SOFF_W1;
    float* W2s   = sm + SOFF_W2;
    float* Xs    = sm + SOFF_X;
    float* s_sum = sm + SOFF_SUM;
    float* s_sq  = sm + SOFF_SQ;
    int*   s_si  = (int*)(sm + SOFF_SI);
    int*   s_ti  = (int*)(sm + SOFF_TI);
    float* s_g   = sm + SOFF_G;
    float* s_b   = sm + SOFF_B;

    const int tid  = threadIdx.x;
    const int wid  = tid >> 5;
    const int lane = tid & 31;
    const int g    = lane >> 2;     // fragment group id
    const int t4   = lane & 3;      // thread-in-group
    const int wr   = wid & 3;       // warp row  (rows wr*32 .. +32)
    const int wc   = wid >> 2;      // warp col  (cols wc*64 .. +64)

    if (tid < 128) { s_g[tid] = gamma[tid]; s_b[tid] = beta[tid]; }

    // stage both weight tiles once (tf32-rounded)
    for (int i = tid; i < 128 * 32; i += 256) {
        int n = i >> 5, k4 = (i & 31) << 2;
        float4 a = *(const float4*)(W1 + n * D + k4);
        float4 b = *(const float4*)(W2 + n * D + k4);
        float* p1 = W1s + n * PAD + k4;
        float* p2 = W2s + n * PAD + k4;
        p1[0] = to_tf32(a.x); p1[1] = to_tf32(a.y); p1[2] = to_tf32(a.z); p1[3] = to_tf32(a.w);
        p2[0] = to_tf32(b.x); p2[1] = to_tf32(b.y); p2[2] = to_tf32(b.z); p2[3] = to_tf32(b.w);
    }
    __syncthreads();

    for (int tile = blockIdx.x; tile < NTILES; tile += gridDim.x) {
        const int m0 = tile * 128;
        if (tid < 128) { s_si[tid] = src_idx[m0 + tid]; s_ti[tid] = tgt_idx[m0 + tid]; }
        __syncthreads();

        // ---- stage X0 = src[si] + tgt[ti] (tf32-rounded) ----
#pragma unroll
        for (int i = tid; i < 128 * 32; i += 256) {
            int row = i >> 5, k4 = (i & 31) << 2;
            float4 a = *(const float4*)(src_feat + (size_t)s_si[row] * D + k4);
            float4 b = *(const float4*)(tgt_feat + (size_t)s_ti[row] * D + k4);
            float* p = Xs + row * PAD + k4;
            p[0] = to_tf32(a.x + b.x); p[1] = to_tf32(a.y + b.y);
            p[2] = to_tf32(a.z + b.z); p[3] = to_tf32(a.w + b.w);
        }
        __syncthreads();

        float acc[2][8][4];
#pragma unroll
        for (int mt = 0; mt < 2; mt++)
#pragma unroll
            for (int nt = 0; nt < 8; nt++)
#pragma unroll
                for (int j = 0; j < 4; j++) acc[mt][nt][j] = 0.f;

        // ---- pass 1: acc += X0 @ W1^T ----
#pragma unroll
        for (int ks = 0; ks < 16; ks++) {
            const int k0 = ks * 8;
            uint32_t afr[2][4];
#pragma unroll
            for (int mt = 0; mt < 2; mt++) {
                const float* ap = Xs + (wr * 32 + mt * 16 + g) * PAD + k0 + t4;
                afr[mt][0] = f2u(ap[0]);
                afr[mt][1] = f2u(ap[8 * PAD]);
                afr[mt][2] = f2u(ap[4]);
                afr[mt][3] = f2u(ap[8 * PAD + 4]);
            }
#pragma unroll
            for (int nt = 0; nt < 8; nt++) {
                const float* bp = W1s + (wc * 64 + nt * 8 + g) * PAD + k0 + t4;
                uint32_t b0 = f2u(bp[0]), b1 = f2u(bp[4]);
                mma8(acc[0][nt], afr[0], b0, b1);
                mma8(acc[1][nt], afr[1], b0, b1);
            }
        }
        __syncthreads();

        // ---- stage X1 = edge_feat (RAW fp32: exact residual; HW truncates for MMA) ----
#pragma unroll
        for (int i = tid; i < 128 * 32; i += 256) {
            int row = i >> 5, k4 = (i & 31) << 2;
            *(float4*)(Xs + row * PAD + k4) =
                *(const float4*)(edge_feat + (size_t)(m0 + row) * D + k4);
        }
        __syncthreads();

        // ---- pass 2: acc += X1 @ W2^T ----
#pragma unroll
        for (int ks = 0; ks < 16; ks++) {
            const int k0 = ks * 8;
            uint32_t afr[2][4];
#pragma unroll
            for (int mt = 0; mt < 2; mt++) {
                const float* ap = Xs + (wr * 32 + mt * 16 + g) * PAD + k0 + t4;
                afr[mt][0] = f2u(ap[0]);
                afr[mt][1] = f2u(ap[8 * PAD]);
                afr[mt][2] = f2u(ap[4]);
                afr[mt][3] = f2u(ap[8 * PAD + 4]);
            }
#pragma unroll
            for (int nt = 0; nt < 8; nt++) {
                const float* bp = W2s + (wc * 64 + nt * 8 + g) * PAD + k0 + t4;
                uint32_t b0 = f2u(bp[0]), b1 = f2u(bp[4]);
                mma8(acc[0][nt], afr[0], b0, b1);
                mma8(acc[1][nt], afr[1], b0, b1);
            }
        }

        // ---- epilogue: silu + LN(partial via quad-shfl + smem) ----
#pragma unroll
        for (int mt = 0; mt < 2; mt++) {
#pragma unroll
            for (int h = 0; h < 2; h++) {
                float s = 0.f, q = 0.f;
#pragma unroll
                for (int nt = 0; nt < 8; nt++) {
#pragma unroll
                    for (int j = 0; j < 2; j++) {
                        float v  = acc[mt][nt][h * 2 + j];
                        float sv = v / (1.f + __expf(-v));
                        acc[mt][nt][h * 2 + j] = sv;
                        s += sv; q += sv * sv;
                    }
                }
                s += __shfl_xor_sync(0xffffffffu, s, 1);
                s += __shfl_xor_sync(0xffffffffu, s, 2);
                q += __shfl_xor_sync(0xffffffffu, q, 1);
                q += __shfl_xor_sync(0xffffffffu, q, 2);
                if (t4 == 0) {
                    int row = wr * 32 + mt * 16 + h * 8 + g;
                    s_sum[wc * 128 + row] = s;
                    s_sq[wc * 128 + row]  = q;
                }
            }
        }
        __syncthreads();

#pragma unroll
        for (int mt = 0; mt < 2; mt++) {
#pragma unroll
            for (int h = 0; h < 2; h++) {
                const int row = wr * 32 + mt * 16 + h * 8 + g;
                const float tsum = s_sum[row] + s_sum[128 + row];
                const float tsq  = s_sq[row]  + s_sq[128 + row];
                const float mean = tsum * (1.f / 128.f);
                const float inv  = rsqrtf(tsq * (1.f / 128.f) - mean * mean + 1e-5f);
                const int    t   = s_ti[row];
                const size_t gm  = (size_t)(m0 + row);
                float* __restrict__ srow = g_sums + (size_t)t * D;
#pragma unroll
                for (int nt = 0; nt < 8; nt++) {
                    const int c = wc * 64 + nt * 8 + t4 * 2;
                    float a0 = (acc[mt][nt][h * 2 + 0] - mean) * inv * s_g[c + 0] + s_b[c + 0];
                    float a1 = (acc[mt][nt][h * 2 + 1] - mean) * inv * s_g[c + 1] + s_b[c + 1];
                    float2 rs = *(const float2*)(Xs + row * PAD + c);
                    float2 o; o.x = rs.x + a0; o.y = rs.y + a1;
                    *(float2*)(out + gm * D + c) = o;
                    atomicAdd(srow + c + 0, a0);
                    atomicAdd(srow + c + 1, a1);
                }
                if (wc == 0 && t4 == 0) atomicAdd(g_counts + t, 1.f);
            }
        }
        __syncthreads();   // protect Xs / s_sum / s_si before next tile
    }
}

// ======================= NODE kernel (SIMT, small) =======================
#define TILE_M  128
#define KC      32
#define SST     132

__global__ void __launch_bounds__(256)
node_kernel(const float* __restrict__ tgt_feat,
            const float* __restrict__ W1,       // We2t
            const float* __restrict__ W2,       // Wt2t
            const float* __restrict__ gamma,
            const float* __restrict__ beta,
            float*       __restrict__ out,
            int M)
{
    __shared__ float xs[KC][SST];
    __shared__ float ws[KC][SST];
    __shared__ float s_inv[TILE_M];

    const int tid = threadIdx.x;
    const int tx  = tid & 15;
    const int ty  = tid >> 4;
    const int m0  = blockIdx.x * TILE_M;

    for (int i = tid; i < TILE_M; i += 256) {
        int row = m0 + i;
        s_inv[i] = (row < M) ? 1.f / fmaxf(g_counts[row], 1.f) : 0.f;
    }
    __syncthreads();

    float acc[8][8];
#pragma unroll
    for (int r = 0; r < 8; r++)
#pragma unroll
        for (int c = 0; c < 8; c++) acc[r][c] = 0.f;

#pragma unroll 1
    for (int pass = 0; pass < 2; pass++) {
        const float* __restrict__ W = pass ? W2 : W1;
#pragma unroll 1
        for (int kc = 0; kc < D / KC; kc++) {
            const int k0 = kc * KC;
            for (int i = tid; i < D * KC; i += 256) {
                int n = i >> 5, kl = i & 31;
                ws[kl][n] = W[n * D + k0 + kl];
            }
            for (int i = tid; i < TILE_M * KC; i += 256) {
                int m = i >> 5, kl = i & 31;
                float v = 0.f;
                long gm = (long)(m0 + m);
                if (gm < M) {
                    if (pass == 0) v = g_sums[gm * D + k0 + kl] * s_inv[m];
                    else           v = tgt_feat[gm * D + k0 + kl];
                }
                xs[kl][m] = v;
            }
            __syncthreads();
#pragma unroll
            for (int k = 0; k < KC; k++) {
                float4 xa = *(const float4*)&xs[k][ty * 4];
                float4 xb = *(const float4*)&xs[k][64 + ty * 4];
                float4 wa = *(const float4*)&ws[k][tx * 4];
                float4 wb = *(const float4*)&ws[k][64 + tx * 4];
                float xv[8] = {xa.x, xa.y, xa.z, xa.w, xb.x, xb.y, xb.z, xb.w};
                float wv[8] = {wa.x, wa.y, wa.z, wa.w, wb.x, wb.y, wb.z, wb.w};
#pragma unroll
                for (int r = 0; r < 8; r++)
#pragma unroll
                    for (int c = 0; c < 8; c++) acc[r][c] += xv[r] * wv[c];
            }
            __syncthreads();
        }
    }

    float g[8], b[8];
#pragma unroll
    for (int c = 0; c < 8; c++) {
        int n = (c < 4) ? (tx * 4 + c) : (64 + tx * 4 + (c - 4));
        g[c] = gamma[n];
        b[c] = beta[n];
    }

#pragma unroll
    for (int r = 0; r < 8; r++) {
        const int mrow = (r < 4) ? (ty * 4 + r) : (64 + ty * 4 + (r - 4));
        const long gm  = (long)(m0 + mrow);

        float sum = 0.f, sq = 0.f;
#pragma unroll
        for (int c = 0; c < 8; c++) {
            float v  = acc[r][c];
            float sv = v / (1.f + __expf(-v));
            acc[r][c] = sv;
            sum += sv; sq += sv * sv;
        }
#pragma unroll
        for (int o = 8; o >= 1; o >>= 1) {
            sum += __shfl_xor_sync(0xffffffffu, sum, o);
            sq  += __shfl_xor_sync(0xffffffffu, sq,  o);
        }
        const float mean = sum * (1.f / 128.f);
        const float var  = sq * (1.f / 128.f) - mean * mean;
        const float inv  = rsqrtf(var + 1e-5f);

        if (gm >= M) continue;

        const float* __restrict__ resrow = tgt_feat + gm * D;
        float4 r0 = *(const float4*)&resrow[tx * 4];
        float4 r1 = *(const float4*)&resrow[64 + tx * 4];
        float a0 = (acc[r][0] - mean) * inv * g[0] + b[0];
        float a1 = (acc[r][1] - mean) * inv * g[1] + b[1];
        float a2 = (acc[r][2] - mean) * inv * g[2] + b[2];
        float a3 = (acc[r][3] - mean) * inv * g[3] + b[3];
        float a4 = (acc[r][4] - mean) * inv * g[4] + b[4];
        float a5 = (acc[r][5] - mean) * inv * g[5] + b[5];
        float a6 = (acc[r][6] - mean) * inv * g[6] + b[6];
        float a7 = (acc[r][7] - mean) * inv * g[7] + b[7];
        *(float4*)&out[gm * D + tx * 4] =
            make_float4(r0.x + a0, r0.y + a1, r0.z + a2, r0.w + a3);
        *(float4*)&out[gm * D + 64 + tx * 4] =
            make_float4(r1.x + a4, r1.y + a5, r1.z + a6, r1.w + a7);
    }
}

// ======================= launch =======================
extern "C" void kernel_launch(void* const* d_in, const int* in_sizes, int n_in,
                              void* d_out, int out_size) {
    const float* src_feat  = (const float*)d_in[0];
    const float* tgt_feat  = (const float*)d_in[1];
    const float* edge_feat = (const float*)d_in[2];
    const float* Ws2e      = (const float*)d_in[3];
    const float* We2e      = (const float*)d_in[4];
    const float* We2t      = (const float*)d_in[5];
    const float* Wt2t      = (const float*)d_in[6];
    const float* gamma1    = (const float*)d_in[7];
    const float* beta1     = (const float*)d_in[8];
    const float* gamma2    = (const float*)d_in[9];
    const float* beta2     = (const float*)d_in[10];
    const int*   src_idx   = (const int*)d_in[11];
    const int*   tgt_idx   = (const int*)d_in[12];
    float*       out       = (float*)d_out;

    cudaFuncSetAttribute(edge_kernel,
                         cudaFuncAttributeMaxDynamicSharedMemorySize, SMEM_BYTES);

    zero_scratch_kernel<<<2048, 256>>>();

    edge_kernel<<<148, 256, SMEM_BYTES>>>(
        src_feat, tgt_feat, edge_feat, Ws2e, We2e, gamma1, beta1,
        src_idx, tgt_idx, out);

    node_kernel<<<(N_TGT + TILE_M - 1) / TILE_M, 256>>>(
        tgt_feat, We2t, Wt2t, gamma2, beta2, out + (size_t)N_EDGE * D, N_TGT);
}